// round 10
// baseline (speedup 1.0000x reference)
#include <cuda_runtime.h>
#include <cuda_bf16.h>
#include <stdint.h>

#define NNODES 8192
#define DIM    256
#define ALPHA  3.0f
#define NEG    0.2f

#define TPB  512                 // softmax threads per block (clean 512 test)
#define CPT  (NNODES / TPB)      // 16 columns per thread
#define VEC4 (CPT / 4)           // 4 float4 groups per thread
#define NWARP (TPB / 32)         // 16 warps

// Scratch (__device__ globals; no cudaMalloc allowed)
__device__ float g_s1[NNODES];
__device__ float g_s2p[NNODES];  // permuted: g_s2p[idx[j]] = s2[j]

// Single-op hardware tanh (sm_75+): MUFU.TANH, rel err ~2^-11 (<< 1e-3 budget)
__device__ __forceinline__ float htanh(float x) {
    float y;
    asm("tanh.approx.f32 %0, %1;" : "=f"(y) : "f"(x));
    return y;
}

// ---------------------------------------------------------------------------
// score: HALF-WARP per node (16 lanes x 16 dims each) — unchanged from R9.
// ---------------------------------------------------------------------------
__global__ void __launch_bounds__(128)
score_kernel(const int* __restrict__ idx,
             const float* __restrict__ e1,
             const float* __restrict__ e2,
             const float* __restrict__ w)
{
    const int node = (blockIdx.x * 128 + threadIdx.x) >> 4;
    const int sub  = threadIdx.x & 15;
    const int src  = __ldg(&idx[node]);

    const float4* r1 = (const float4*)(e1 + (size_t)src * DIM);
    const float4* r2 = (const float4*)(e2 + (size_t)src * DIM);
    const float4* w1 = (const float4*)(w);
    const float4* w2 = (const float4*)(w + DIM);

    float p1 = 0.f, p2 = 0.f;
    #pragma unroll
    for (int q = 0; q < 4; q++) {
        const int k = sub + 16 * q;                 // interleaved -> coalesced
        float4 a  = r1[k];
        float4 b  = r2[k];
        float4 wa = __ldg(&w1[k]);
        float4 wb = __ldg(&w2[k]);
        p1 += htanh(ALPHA * a.x) * wa.x + htanh(ALPHA * a.y) * wa.y
            + htanh(ALPHA * a.z) * wa.z + htanh(ALPHA * a.w) * wa.w;
        p2 += htanh(ALPHA * b.x) * wb.x + htanh(ALPHA * b.y) * wb.y
            + htanh(ALPHA * b.z) * wb.z + htanh(ALPHA * b.w) * wb.w;
    }
    #pragma unroll
    for (int o = 8; o > 0; o >>= 1) {
        p1 += __shfl_xor_sync(0xffffffffu, p1, o);
        p2 += __shfl_xor_sync(0xffffffffu, p2, o);
    }
    if (sub == 0) {
        g_s1[node] = p1;
        g_s2p[src] = p2;
    }
}

// ---------------------------------------------------------------------------
// softmax: one block per row i. 512 threads x 16 cols (vals[16] -> ~32 regs
// -> ~100% occupancy). Same math as R5/R9: no max subtraction, one exp per
// element, one block sum, plain contiguous float4 stores (NO __stcs).
// ---------------------------------------------------------------------------
__global__ void __launch_bounds__(TPB)
softmax_kernel(const float* __restrict__ att_b,
               float* __restrict__ out)
{
    const int i = blockIdx.x;
    const int t = threadIdx.x;

    const float base = g_s1[i] + att_b[0];
    const float4* s2p4 = (const float4*)g_s2p;

    float vals[CPT];
    float sum = 0.f;
    #pragma unroll
    for (int q = 0; q < VEC4; q++) {
        float4 s = __ldg(&s2p4[q * TPB + t]);
        #pragma unroll
        for (int u = 0; u < 4; u++) {
            float x = base + ((const float*)&s)[u];
            x = (x > 0.f) ? x : NEG * x;      // leaky_relu
            float e = __expf(x);
            vals[q * 4 + u] = e;
            sum += e;
        }
    }

    // block sum (16 warps)
    __shared__ float shs[NWARP];
    #pragma unroll
    for (int o = 16; o > 0; o >>= 1)
        sum += __shfl_xor_sync(0xffffffffu, sum, o);
    if ((t & 31) == 0) shs[t >> 5] = sum;
    __syncthreads();
    sum = 0.f;
    #pragma unroll
    for (int wgi = 0; wgi < NWARP; wgi++) sum += shs[wgi];

    const float inv = __frcp_rn(sum);

    // plain contiguous float4 stores
    float4* row4 = (float4*)(out + (size_t)i * NNODES);
    #pragma unroll
    for (int q = 0; q < VEC4; q++) {
        float4 v;
        v.x = vals[q * 4 + 0] * inv;
        v.y = vals[q * 4 + 1] * inv;
        v.z = vals[q * 4 + 2] * inv;
        v.w = vals[q * 4 + 3] * inv;
        row4[q * TPB + t] = v;
    }
}

// ---------------------------------------------------------------------------
// Inputs: idx[int32 N], emb1_w[f32 N*D], emb2_w[f32 N*D], att_w[f32 2D],
//         att_b[f32 1].  Output: f32 N*N.
// ---------------------------------------------------------------------------
extern "C" void kernel_launch(void* const* d_in, const int* in_sizes, int n_in,
                              void* d_out, int out_size)
{
    const int*   idx  = (const int*)  d_in[0];
    const float* e1   = (const float*)d_in[1];
    const float* e2   = (const float*)d_in[2];
    const float* attw = (const float*)d_in[3];
    const float* attb = (const float*)d_in[4];
    float*       out  = (float*)d_out;

    score_kernel<<<NNODES * 16 / 128, 128>>>(idx, e1, e2, attw);
    softmax_kernel<<<NNODES, TPB>>>(attb, out);
}